// round 1
// baseline (speedup 1.0000x reference)
#include <cuda_runtime.h>
#include <math.h>

#define Bb   16
#define Ss   1024
#define Ee   256
#define Hh   256
#define FHh  512
#define Vv   8000
#define WSw  5
#define NTOK (Bb*Ss)     /* 16384 */
#define G4H  (4*Hh)      /* 1024  */

// ---------------- scratch (device globals; no dynamic allocation) ----------
__device__ float g_PV[2][(size_t)Vv * G4H];     // per-vocab input projections (2 dirs)
__device__ float g_G [(size_t)NTOK * G4H];      // gate pre-activations for one step
__device__ float g_h [(size_t)NTOK * Hh];       // running h
__device__ float g_c [(size_t)NTOK * Hh];       // running c
__device__ float g_hf[(size_t)NTOK * Hh];       // final forward h
__device__ float g_hb[(size_t)NTOK * Hh];       // final backward h
__device__ float g_fc1[(size_t)NTOK * FHh];     // fc1 activations

__device__ __forceinline__ float sigmoidf_(float x) { return 1.0f / (1.0f + expf(-x)); }
__device__ __forceinline__ float leakyf_(float x)   { return x > 0.0f ? x : 0.01f * x; }

// ---------------------------------------------------------------------------
// PV precompute: g_PV[dir][v][j] = sum_e table[v][e] * Wih[j][e], table row0=0
// C = A(8000x256) * B(1024x256)^T ; 64x64x16 tiles, 4x4 microtile.
// ---------------------------------------------------------------------------
__global__ void __launch_bounds__(256) pv_gemm(const float* __restrict__ embed,
                                               const float* __restrict__ Wih,
                                               int dir)
{
    __shared__ float As[16][64];
    __shared__ float Bs[16][64];
    const int tid = threadIdx.x;
    const int lr = tid >> 2;            // 0..63
    const int lc = (tid & 3) << 2;      // 0,4,8,12
    const int m0 = blockIdx.y * 64, n0 = blockIdx.x * 64;
    const int ty = tid >> 4, tx = tid & 15;
    float acc[4][4] = {};

    for (int k0 = 0; k0 < Ee; k0 += 16) {
        const int ar = m0 + lr;
        float4 a;
        if (ar == 0) a = make_float4(0.f, 0.f, 0.f, 0.f);     // embed.at[0].set(0)
        else         a = *(const float4*)(embed + (size_t)ar * Ee + k0 + lc);
        As[lc + 0][lr] = a.x; As[lc + 1][lr] = a.y; As[lc + 2][lr] = a.z; As[lc + 3][lr] = a.w;
        float4 b = *(const float4*)(Wih + (size_t)(n0 + lr) * Ee + k0 + lc);
        Bs[lc + 0][lr] = b.x; Bs[lc + 1][lr] = b.y; Bs[lc + 2][lr] = b.z; Bs[lc + 3][lr] = b.w;
        __syncthreads();
#pragma unroll
        for (int kk = 0; kk < 16; kk++) {
            float4 av = *(const float4*)&As[kk][ty << 2];
            float4 bv = *(const float4*)&Bs[kk][tx << 2];
            acc[0][0] += av.x * bv.x; acc[0][1] += av.x * bv.y; acc[0][2] += av.x * bv.z; acc[0][3] += av.x * bv.w;
            acc[1][0] += av.y * bv.x; acc[1][1] += av.y * bv.y; acc[1][2] += av.y * bv.z; acc[1][3] += av.y * bv.w;
            acc[2][0] += av.z * bv.x; acc[2][1] += av.z * bv.y; acc[2][2] += av.z * bv.z; acc[2][3] += av.z * bv.w;
            acc[3][0] += av.w * bv.x; acc[3][1] += av.w * bv.y; acc[3][2] += av.w * bv.z; acc[3][3] += av.w * bv.w;
        }
        __syncthreads();
    }
    float* out = g_PV[dir];
#pragma unroll
    for (int i = 0; i < 4; i++) {
        const int m = m0 + (ty << 2) + i;
        float4 v = make_float4(acc[i][0], acc[i][1], acc[i][2], acc[i][3]);
        *(float4*)(out + (size_t)m * G4H + n0 + (tx << 2)) = v;
    }
}

// ---------------------------------------------------------------------------
// Recurrent gate GEMM: G[n][j] = h[n] . Whh[j] + bih[j]+bhh[j] + PV[tok(n,step)][j]
// M=16384, N=1024, K=256
// ---------------------------------------------------------------------------
__global__ void __launch_bounds__(256) gates_gemm(const float* __restrict__ Whh,
                                                  const float* __restrict__ bih,
                                                  const float* __restrict__ bhh,
                                                  const int*   __restrict__ x,
                                                  int step, int dir)
{
    __shared__ float As[16][64];
    __shared__ float Bs[16][64];
    const int tid = threadIdx.x;
    const int lr = tid >> 2;
    const int lc = (tid & 3) << 2;
    const int m0 = blockIdx.y * 64, n0 = blockIdx.x * 64;
    const int ty = tid >> 4, tx = tid & 15;
    float acc[4][4] = {};

    for (int k0 = 0; k0 < Hh; k0 += 16) {
        float4 a = *(const float4*)(g_h + (size_t)(m0 + lr) * Hh + k0 + lc);
        As[lc + 0][lr] = a.x; As[lc + 1][lr] = a.y; As[lc + 2][lr] = a.z; As[lc + 3][lr] = a.w;
        float4 b = *(const float4*)(Whh + (size_t)(n0 + lr) * Hh + k0 + lc);
        Bs[lc + 0][lr] = b.x; Bs[lc + 1][lr] = b.y; Bs[lc + 2][lr] = b.z; Bs[lc + 3][lr] = b.w;
        __syncthreads();
#pragma unroll
        for (int kk = 0; kk < 16; kk++) {
            float4 av = *(const float4*)&As[kk][ty << 2];
            float4 bv = *(const float4*)&Bs[kk][tx << 2];
            acc[0][0] += av.x * bv.x; acc[0][1] += av.x * bv.y; acc[0][2] += av.x * bv.z; acc[0][3] += av.x * bv.w;
            acc[1][0] += av.y * bv.x; acc[1][1] += av.y * bv.y; acc[1][2] += av.y * bv.z; acc[1][3] += av.y * bv.w;
            acc[2][0] += av.z * bv.x; acc[2][1] += av.z * bv.y; acc[2][2] += av.z * bv.z; acc[2][3] += av.z * bv.w;
            acc[3][0] += av.w * bv.x; acc[3][1] += av.w * bv.y; acc[3][2] += av.w * bv.z; acc[3][3] += av.w * bv.w;
        }
        __syncthreads();
    }

    const int cbase = n0 + (tx << 2);
    const float4 bi = *(const float4*)(bih + cbase);
    const float4 bh = *(const float4*)(bhh + cbase);
#pragma unroll
    for (int i = 0; i < 4; i++) {
        const int n = m0 + (ty << 2) + i;
        const int bidx = n >> 10;              // S = 1024
        const int t    = n & (Ss - 1);
        const int tp   = (dir == 0) ? (t - WSw + step) : (t + WSw - step);
        const bool valid = ((unsigned)tp < (unsigned)Ss);
        float4 v = make_float4(acc[i][0] + bi.x + bh.x,
                               acc[i][1] + bi.y + bh.y,
                               acc[i][2] + bi.z + bh.z,
                               acc[i][3] + bi.w + bh.w);
        if (valid) {
            const int tok = x[(bidx << 10) + tp];
            float4 pv = *(const float4*)(&g_PV[dir][(size_t)tok * G4H + cbase]);
            v.x += pv.x; v.y += pv.y; v.z += pv.z; v.w += pv.w;
        }
        *(float4*)(g_G + (size_t)n * G4H + cbase) = v;
    }
}

// ---------------------------------------------------------------------------
// LSTM cell update: c = sig(f)*c + sig(i)*tanh(g); h = sig(o)*tanh(c)
// dst_sel: 0 -> g_h, 1 -> g_hf, 2 -> g_hb
// ---------------------------------------------------------------------------
__global__ void __launch_bounds__(256) gate_update(int dst_sel)
{
    const int idx = blockIdx.x * blockDim.x + threadIdx.x;
    if (idx >= NTOK * Hh / 4) return;
    const int n  = idx >> 6;           // Hh/4 = 64
    const int j4 = (idx & 63) << 2;
    const float* Gr = g_G + (size_t)n * G4H;
    float4 iv = *(const float4*)(Gr + j4);
    float4 fv = *(const float4*)(Gr + Hh + j4);
    float4 gv = *(const float4*)(Gr + 2 * Hh + j4);
    float4 ov = *(const float4*)(Gr + 3 * Hh + j4);
    float4 cv = *(const float4*)(g_c + (size_t)n * Hh + j4);

    float4 cn, hn;
    cn.x = sigmoidf_(fv.x) * cv.x + sigmoidf_(iv.x) * tanhf(gv.x);
    cn.y = sigmoidf_(fv.y) * cv.y + sigmoidf_(iv.y) * tanhf(gv.y);
    cn.z = sigmoidf_(fv.z) * cv.z + sigmoidf_(iv.z) * tanhf(gv.z);
    cn.w = sigmoidf_(fv.w) * cv.w + sigmoidf_(iv.w) * tanhf(gv.w);
    hn.x = sigmoidf_(ov.x) * tanhf(cn.x);
    hn.y = sigmoidf_(ov.y) * tanhf(cn.y);
    hn.z = sigmoidf_(ov.z) * tanhf(cn.z);
    hn.w = sigmoidf_(ov.w) * tanhf(cn.w);

    *(float4*)(g_c + (size_t)n * Hh + j4) = cn;
    float* hout = (dst_sel == 0) ? g_h : (dst_sel == 1 ? g_hf : g_hb);
    *(float4*)(hout + (size_t)n * Hh + j4) = hn;
}

__global__ void __launch_bounds__(256) zero_hc()
{
    const int idx = blockIdx.x * blockDim.x + threadIdx.x;
    if (idx < NTOK * Hh / 4) {
        ((float4*)g_h)[idx] = make_float4(0.f, 0.f, 0.f, 0.f);
        ((float4*)g_c)[idx] = make_float4(0.f, 0.f, 0.f, 0.f);
    }
}

// ---------------------------------------------------------------------------
// fc1: g_fc1[n][j] = leaky( leaky(concat(hf,hb))[n] . fc1_w[j] + fc1_b[j] )
// M=16384, N=512, K=512
// ---------------------------------------------------------------------------
__global__ void __launch_bounds__(256) fc1_gemm(const float* __restrict__ fc1_w,
                                                const float* __restrict__ fc1_b)
{
    __shared__ float As[16][64];
    __shared__ float Bs[16][64];
    const int tid = threadIdx.x;
    const int lr = tid >> 2;
    const int lc = (tid & 3) << 2;
    const int m0 = blockIdx.y * 64, n0 = blockIdx.x * 64;
    const int ty = tid >> 4, tx = tid & 15;
    float acc[4][4] = {};

    for (int k0 = 0; k0 < 2 * Hh; k0 += 16) {
        const int n = m0 + lr;
        const int kk = k0 + lc;
        const float* src = (kk < Hh) ? (g_hf + (size_t)n * Hh + kk)
                                     : (g_hb + (size_t)n * Hh + (kk - Hh));
        float4 a = *(const float4*)src;
        a.x = leakyf_(a.x); a.y = leakyf_(a.y); a.z = leakyf_(a.z); a.w = leakyf_(a.w);
        As[lc + 0][lr] = a.x; As[lc + 1][lr] = a.y; As[lc + 2][lr] = a.z; As[lc + 3][lr] = a.w;
        float4 b = *(const float4*)(fc1_w + (size_t)(n0 + lr) * (2 * Hh) + k0 + lc);
        Bs[lc + 0][lr] = b.x; Bs[lc + 1][lr] = b.y; Bs[lc + 2][lr] = b.z; Bs[lc + 3][lr] = b.w;
        __syncthreads();
#pragma unroll
        for (int kkk = 0; kkk < 16; kkk++) {
            float4 av = *(const float4*)&As[kkk][ty << 2];
            float4 bv = *(const float4*)&Bs[kkk][tx << 2];
            acc[0][0] += av.x * bv.x; acc[0][1] += av.x * bv.y; acc[0][2] += av.x * bv.z; acc[0][3] += av.x * bv.w;
            acc[1][0] += av.y * bv.x; acc[1][1] += av.y * bv.y; acc[1][2] += av.y * bv.z; acc[1][3] += av.y * bv.w;
            acc[2][0] += av.z * bv.x; acc[2][1] += av.z * bv.y; acc[2][2] += av.z * bv.z; acc[2][3] += av.z * bv.w;
            acc[3][0] += av.w * bv.x; acc[3][1] += av.w * bv.y; acc[3][2] += av.w * bv.z; acc[3][3] += av.w * bv.w;
        }
        __syncthreads();
    }

    const int cbase = n0 + (tx << 2);
    const float4 fb = *(const float4*)(fc1_b + cbase);
#pragma unroll
    for (int i = 0; i < 4; i++) {
        const int m = m0 + (ty << 2) + i;
        float4 v = make_float4(leakyf_(acc[i][0] + fb.x),
                               leakyf_(acc[i][1] + fb.y),
                               leakyf_(acc[i][2] + fb.z),
                               leakyf_(acc[i][3] + fb.w));
        *(float4*)(g_fc1 + (size_t)m * FHh + cbase) = v;
    }
}

// ---------------------------------------------------------------------------
// fc2: out[n] = sigmoid( g_fc1[n] . fc2_w + fc2_b )
// ---------------------------------------------------------------------------
__global__ void __launch_bounds__(128) fc2_kernel(const float* __restrict__ w,
                                                  const float* __restrict__ b,
                                                  float* __restrict__ out)
{
    const int n = blockIdx.x;
    const int t = threadIdx.x;
    const float* row = g_fc1 + (size_t)n * FHh;
    float s = 0.f;
#pragma unroll
    for (int j = t; j < FHh; j += 128) s += row[j] * w[j];
#pragma unroll
    for (int o = 16; o > 0; o >>= 1) s += __shfl_xor_sync(0xffffffffu, s, o);
    __shared__ float ws[4];
    if ((t & 31) == 0) ws[t >> 5] = s;
    __syncthreads();
    if (t == 0) {
        const float tot = ws[0] + ws[1] + ws[2] + ws[3];
        out[n] = 1.0f / (1.0f + expf(-(tot + b[0])));
    }
}

// ---------------------------------------------------------------------------
extern "C" void kernel_launch(void* const* d_in, const int* in_sizes, int n_in,
                              void* d_out, int out_size)
{
    const int*   x      = (const int*)  d_in[0];
    const float* embed  = (const float*)d_in[1];
    const float* Wih_f  = (const float*)d_in[2];
    const float* Whh_f  = (const float*)d_in[3];
    const float* bih_f  = (const float*)d_in[4];
    const float* bhh_f  = (const float*)d_in[5];
    const float* Wih_b  = (const float*)d_in[6];
    const float* Whh_b  = (const float*)d_in[7];
    const float* bih_b  = (const float*)d_in[8];
    const float* bhh_b  = (const float*)d_in[9];
    const float* fc1_w  = (const float*)d_in[10];
    const float* fc1_b  = (const float*)d_in[11];
    const float* fc2_w  = (const float*)d_in[12];
    const float* fc2_b  = (const float*)d_in[13];
    float* out = (float*)d_out;

    const dim3 thr(256);

    // Precompute per-vocab input projections for both directions.
    pv_gemm<<<dim3(G4H / 64, Vv / 64), thr>>>(embed, Wih_f, 0);
    pv_gemm<<<dim3(G4H / 64, Vv / 64), thr>>>(embed, Wih_b, 1);

    const int hc_blocks = (NTOK * Hh / 4 + 255) / 256;

    for (int dir = 0; dir < 2; dir++) {
        zero_hc<<<hc_blocks, 256>>>();
        const float* Whh = dir ? Whh_b : Whh_f;
        const float* bi  = dir ? bih_b : bih_f;
        const float* bh  = dir ? bhh_b : bhh_f;
        for (int k = 0; k <= WSw; k++) {
            gates_gemm<<<dim3(G4H / 64, NTOK / 64), thr>>>(Whh, bi, bh, x, k, dir);
            const int dst = (k == WSw) ? (dir ? 2 : 1) : 0;
            gate_update<<<hc_blocks, 256>>>(dst);
        }
    }

    fc1_gemm<<<dim3(FHh / 64, NTOK / 64), thr>>>(fc1_w, fc1_b);
    fc2_kernel<<<NTOK, 128>>>(fc2_w, fc2_b, out);
}

// round 7
// speedup vs baseline: 1.7041x; 1.7041x over previous
#include <cuda_runtime.h>
#include <cuda_bf16.h>
#include <math.h>
#include <stdint.h>

#define Bb   16
#define Ss   1024
#define Ee   256
#define Hh   256
#define FHh  512
#define Vv   8000
#define WSw  5
#define NTOK (Bb*Ss)     /* 16384 */
#define G4H  (4*Hh)      /* 1024  */

// ---------------- scratch (device globals; no dynamic allocation) ----------
__device__ float g_PVp[2][(size_t)Vv * G4H];            // permuted-col input projections
__device__ __nv_bfloat16 g_hA[2][2][2][(size_t)NTOK * Hh];  // [dir][pingpong][hi/lo] h as bf16
__device__ float g_cst[2][(size_t)NTOK * Hh];           // [dir] c state
__device__ float g_hf[(size_t)NTOK * Hh];               // final fwd h (fp32)
__device__ float g_hb[(size_t)NTOK * Hh];               // final bwd h (fp32)
__device__ float g_fc1[(size_t)NTOK * FHh];
// Whh pre-split bf16 hi/lo, col-permuted, pre-swizzled: [dir][hl][nblk8][kc4][16KB]
__device__ unsigned char g_Bsw[2][2][8][4][16384];
__device__ float g_bsum[2][G4H];                        // permuted bih+bhh

__device__ __forceinline__ float sigmoidf_(float x) { return 1.0f / (1.0f + expf(-x)); }
__device__ __forceinline__ float leakyf_(float x)   { return x > 0.0f ? x : 0.01f * x; }
__device__ __forceinline__ uint32_t swz128(uint32_t off) { return off ^ ((off >> 3) & 0x70); }
__device__ __forceinline__ uint32_t smem_u32(const void* p) {
    uint32_t a;
    asm("{ .reg .u64 t; cvta.to.shared.u64 t, %1; cvt.u32.u64 %0, t; }" : "=r"(a) : "l"(p));
    return a;
}
__device__ __forceinline__ void ldsm4(uint32_t* r, uint32_t addr) {
    asm volatile("ldmatrix.sync.aligned.m8n8.x4.shared.b16 {%0,%1,%2,%3}, [%4];"
        : "=r"(r[0]), "=r"(r[1]), "=r"(r[2]), "=r"(r[3]) : "r"(addr));
}
__device__ __forceinline__ void mma_bf16(float* d, const uint32_t* a, const uint32_t* b) {
    asm volatile("mma.sync.aligned.m16n8k16.row.col.f32.bf16.bf16.f32 "
        "{%0,%1,%2,%3}, {%4,%5,%6,%7}, {%8,%9}, {%0,%1,%2,%3};"
        : "+f"(d[0]), "+f"(d[1]), "+f"(d[2]), "+f"(d[3])
        : "r"(a[0]), "r"(a[1]), "r"(a[2]), "r"(a[3]), "r"(b[0]), "r"(b[1]));
}
__device__ __forceinline__ uint32_t packbf(__nv_bfloat16 a, __nv_bfloat16 b) {
    unsigned short ua = *(unsigned short*)&a, ub = *(unsigned short*)&b;
    return (uint32_t)ua | ((uint32_t)ub << 16);
}

// ---------------------------------------------------------------------------
// prep: split Whh into bf16 hi/lo, permute rows p = unit*4+gate
// (n = gate*256+unit), write pre-swizzled 128-row x 64-k tiles; bias sums.
// ---------------------------------------------------------------------------
__global__ void __launch_bounds__(256) prep_whh(const float* __restrict__ Wf, const float* __restrict__ Wb,
                                                const float* __restrict__ bihf, const float* __restrict__ bhhf,
                                                const float* __restrict__ bihb, const float* __restrict__ bhhb)
{
    int idx = blockIdx.x * 256 + threadIdx.x;        // 2*1024*32 = 65536 threads
    int dir = idx >> 15;
    int r = idx & 32767;
    int n = r >> 5;
    int k8 = (r & 31) << 3;
    const float* W = dir ? Wb : Wf;
    int p = ((n & 255) << 2) | (n >> 8);             // unit*4 + gate
    int nblk = p >> 7, prow = p & 127;
    float4 v0 = *(const float4*)(W + (size_t)n * Hh + k8);
    float4 v1 = *(const float4*)(W + (size_t)n * Hh + k8 + 4);
    float vals[8] = {v0.x, v0.y, v0.z, v0.w, v1.x, v1.y, v1.z, v1.w};
#pragma unroll
    for (int j = 0; j < 8; j++) {
        int k = k8 + j;
        int kc = k >> 6, kb = k & 63;
        uint32_t off = swz128((uint32_t)prow * 128u + (uint32_t)kb * 2u);
        __nv_bfloat16 hi = __float2bfloat16(vals[j]);
        __nv_bfloat16 lo = __float2bfloat16(vals[j] - __bfloat162float(hi));
        *(__nv_bfloat16*)(&g_Bsw[dir][0][nblk][kc][off]) = hi;
        *(__nv_bfloat16*)(&g_Bsw[dir][1][nblk][kc][off]) = lo;
    }
    if (k8 == 0) {
        const float* bi = dir ? bihb : bihf;
        const float* bh = dir ? bhhb : bhhf;
        g_bsum[dir][p] = bi[n] + bh[n];
    }
}

// ---------------------------------------------------------------------------
// PV precompute (fp32 SIMT, permuted-column output)
// ---------------------------------------------------------------------------
__global__ void __launch_bounds__(256) pv_gemm(const float* __restrict__ embed,
                                               const float* __restrict__ Wih, int dir)
{
    __shared__ float As[16][64];
    __shared__ float Bs[16][64];
    const int tid = threadIdx.x;
    const int lr = tid >> 2;
    const int lc = (tid & 3) << 2;
    const int m0 = blockIdx.y * 64, n0 = blockIdx.x * 64;
    const int ty = tid >> 4, tx = tid & 15;
    float acc[4][4] = {};

    for (int k0 = 0; k0 < Ee; k0 += 16) {
        const int arow = m0 + lr;
        float4 a;
        if (arow == 0) a = make_float4(0.f, 0.f, 0.f, 0.f);
        else           a = *(const float4*)(embed + (size_t)arow * Ee + k0 + lc);
        As[lc + 0][lr] = a.x; As[lc + 1][lr] = a.y; As[lc + 2][lr] = a.z; As[lc + 3][lr] = a.w;
        float4 b = *(const float4*)(Wih + (size_t)(n0 + lr) * Ee + k0 + lc);
        Bs[lc + 0][lr] = b.x; Bs[lc + 1][lr] = b.y; Bs[lc + 2][lr] = b.z; Bs[lc + 3][lr] = b.w;
        __syncthreads();
#pragma unroll
        for (int kk = 0; kk < 16; kk++) {
            float4 av = *(const float4*)&As[kk][ty << 2];
            float4 bv = *(const float4*)&Bs[kk][tx << 2];
            acc[0][0] += av.x * bv.x; acc[0][1] += av.x * bv.y; acc[0][2] += av.x * bv.z; acc[0][3] += av.x * bv.w;
            acc[1][0] += av.y * bv.x; acc[1][1] += av.y * bv.y; acc[1][2] += av.y * bv.z; acc[1][3] += av.y * bv.w;
            acc[2][0] += av.z * bv.x; acc[2][1] += av.z * bv.y; acc[2][2] += av.z * bv.z; acc[2][3] += av.z * bv.w;
            acc[3][0] += av.w * bv.x; acc[3][1] += av.w * bv.y; acc[3][2] += av.w * bv.z; acc[3][3] += av.w * bv.w;
        }
        __syncthreads();
    }
    float* out = g_PVp[dir];
    const int cbase = n0 + (tx << 2);
#pragma unroll
    for (int i = 0; i < 4; i++) {
        const int m = m0 + (ty << 2) + i;
#pragma unroll
        for (int j = 0; j < 4; j++) {
            int n = cbase + j;
            int pcol = ((n & 255) << 2) | (n >> 8);
            out[(size_t)m * G4H + pcol] = acc[i][j];
        }
    }
}

// ---------------------------------------------------------------------------
// zero h (buf0 hi/lo, both dirs) and c (both dirs)
// ---------------------------------------------------------------------------
__global__ void __launch_bounds__(256) zero_state()
{
    const int i = blockIdx.x * 256 + threadIdx.x;    // 4,194,304 uint4 total
    const uint4 z = make_uint4(0u, 0u, 0u, 0u);
    if (i < 2097152) {
        int slice = i >> 19;                          // 524288 uint4 per bf16 slice
        int dir = slice >> 1, hl = slice & 1;
        ((uint4*)g_hA[dir][0][hl])[i & 524287] = z;
    } else {
        int j = i - 2097152;                          // 1,048,576 uint4 per c slice
        int dir = j >> 20;
        ((uint4*)g_cst[dir])[j & 1048575] = z;
    }
}

// ---------------------------------------------------------------------------
// gates_mma: one LSTM step, both dirs. CTA tile M=128 x N=128 permuted cols,
// K=256 in 4 chunks of 64. bf16 hi/lo 3-term mma.sync; smem-staged epilogue
// does bias + PV gather + LSTM cell update, writes h as bf16 hi/lo.
// smem: [0,16K) A_hi | [16K,32K) A_lo | [32K,48K) B_hi | [48K,64K) B_lo
//       (union with 64KB fp32 Acc) | [64K, +512) bias
// ---------------------------------------------------------------------------
#define GM_SMEM (1024 + 65536 + 512)

__global__ void __launch_bounds__(256) gates_mma(const int* __restrict__ x, int step)
{
    extern __shared__ unsigned char smraw[];
    uint32_t sb0 = smem_u32(smraw);
    uint32_t sb = (sb0 + 1023u) & ~1023u;
    unsigned char* smb = smraw + (sb - sb0);

    const int dir = blockIdx.z;
    const int nblk = blockIdx.x;               // 8 blocks of 128 permuted cols
    const int m0 = blockIdx.y << 7;            // 128 rows
    const int tid = threadIdx.x;
    const int lane = tid & 31, wid = tid >> 5;
    const int wm = wid >> 2, wn = wid & 3;     // warp grid 2x4, warp tile 64x32
    const int buf = step & 1, nbuf = buf ^ 1;

    float* biasf = (float*)(smb + 65536);
    if (tid < 32)
        *(float4*)(biasf + (tid << 2)) = *(const float4*)(g_bsum[dir] + (nblk << 7) + (tid << 2));

    float acc[4][4][4];
#pragma unroll
    for (int a = 0; a < 4; a++)
#pragma unroll
        for (int b = 0; b < 4; b++)
#pragma unroll
            for (int c = 0; c < 4; c++) acc[a][b][c] = 0.f;

    const uint32_t aBaseH = sb, aBaseL = sb + 16384u, bBaseH = sb + 32768u, bBaseL = sb + 49152u;
    const int arow = (wm << 6) + (lane & 15);
    const int atop = (lane >> 4) << 4;
    const int brow = (wn << 5) + (lane & 7) + ((lane & 16) ? 8 : 0);
    const int btop = (lane & 8) ? 16 : 0;

    for (int kc = 0; kc < 4; kc++) {
        // ---- load A hi/lo (global bf16 row-major, 256 cols) into swizzled smem
#pragma unroll
        for (int hl = 0; hl < 2; hl++) {
            const uint4* src = (const uint4*)g_hA[dir][buf][hl];
            unsigned char* dst = smb + hl * 16384;
#pragma unroll
            for (int i = 0; i < 4; i++) {
                int u = tid + (i << 8);               // 0..1023
                int r = u >> 3, c16 = u & 7;
                uint4 v = src[(size_t)(m0 + r) * 32 + (kc << 3) + c16];
                *(uint4*)(dst + swz128((uint32_t)r * 128u + ((uint32_t)c16 << 4))) = v;
            }
        }
        // ---- load B hi/lo (pre-swizzled 16KB tiles): straight copy
#pragma unroll
        for (int hl = 0; hl < 2; hl++) {
            const uint4* src = (const uint4*)&g_Bsw[dir][hl][nblk][kc][0];
            uint4* dst = (uint4*)(smb + 32768 + hl * 16384);
#pragma unroll
            for (int i = 0; i < 4; i++) dst[tid + (i << 8)] = src[tid + (i << 8)];
        }
        __syncthreads();

#pragma unroll
        for (int ks = 0; ks < 4; ks++) {
            const uint32_t kbyte = (uint32_t)ks << 5;
            uint32_t ah[4][4], al[4][4], bh[8], bl[8];
#pragma unroll
            for (int mi = 0; mi < 4; mi++) {
                uint32_t off = swz128((uint32_t)(arow + mi * 16) * 128u + kbyte + (uint32_t)atop);
                ldsm4(ah[mi], aBaseH + off);
                ldsm4(al[mi], aBaseL + off);
            }
#pragma unroll
            for (int bi = 0; bi < 2; bi++) {
                uint32_t off = swz128((uint32_t)(brow + bi * 16) * 128u + kbyte + (uint32_t)btop);
                ldsm4(bh + bi * 4, bBaseH + off);
                ldsm4(bl + bi * 4, bBaseL + off);
            }
#pragma unroll
            for (int mi = 0; mi < 4; mi++)
#pragma unroll
                for (int ni = 0; ni < 4; ni++) {
                    mma_bf16(acc[mi][ni], ah[mi], bh + ni * 2);
                    mma_bf16(acc[mi][ni], ah[mi], bl + ni * 2);
                    mma_bf16(acc[mi][ni], al[mi], bh + ni * 2);
                }
        }
        __syncthreads();
    }

    // ---- stage accumulators into smem (union over operand tiles)
    float* Acc = (float*)smb;
#pragma unroll
    for (int mi = 0; mi < 4; mi++)
#pragma unroll
        for (int ni = 0; ni < 4; ni++) {
            int r0 = (wm << 6) + mi * 16 + (lane >> 2);
            int c0 = (wn << 5) + ni * 8 + ((lane & 3) << 1);
            *(float2*)(Acc + r0 * 128 + c0) = make_float2(acc[mi][ni][0], acc[mi][ni][1]);
            *(float2*)(Acc + (r0 + 8) * 128 + c0) = make_float2(acc[mi][ni][2], acc[mi][ni][3]);
        }
    __syncthreads();

    // ---- fused epilogue: 2 threads per row, 16 units each
    const int row_l = tid >> 1;
    const int half = tid & 1;
    const int row = m0 + row_l;
    const int t = row & (Ss - 1), bidx = row >> 10;
    const int tp = dir ? (t + WSw - step) : (t - WSw + step);
    const bool valid = ((unsigned)tp < (unsigned)Ss);
    const int tok = valid ? x[(bidx << 10) + tp] : 0;
    const bool finalstep = (step == WSw);

    const float4* accu = (const float4*)(Acc + row_l * 128 + (half << 6));
    const float4* bsu  = (const float4*)(biasf + (half << 6));
    const float4* pvu  = (const float4*)(g_PVp[dir] + (size_t)tok * G4H + (nblk << 7) + (half << 6));
    float4* cp = (float4*)(g_cst[dir] + (size_t)row * Hh + (nblk << 5) + (half << 4));
    const int colbase = (nblk << 5) + (half << 4);    // unit_global base
    __nv_bfloat16* hip = g_hA[dir][nbuf][0] + (size_t)row * Hh + colbase;
    __nv_bfloat16* lop = g_hA[dir][nbuf][1] + (size_t)row * Hh + colbase;
    float* fp = (dir ? g_hb : g_hf) + (size_t)row * Hh + colbase;

    uint32_t hwH[8], hwL[8];
#pragma unroll
    for (int g4 = 0; g4 < 4; g4++) {
        float4 cv = cp[g4];
        float cin[4] = {cv.x, cv.y, cv.z, cv.w};
        float ho[4];
#pragma unroll
        for (int j = 0; j < 4; j++) {
            int u = g4 * 4 + j;
            float4 gq = accu[u];
            float4 bq = bsu[u];
            float pi = gq.x + bq.x, pf = gq.y + bq.y, pg = gq.z + bq.z, po = gq.w + bq.w;
            if (valid) {
                float4 pq = pvu[u];
                pi += pq.x; pf += pq.y; pg += pq.z; po += pq.w;
            }
            float iv = sigmoidf_(pi), fv = sigmoidf_(pf), gv = tanhf(pg), ov = sigmoidf_(po);
            float cn = fv * cin[j] + iv * gv;
            cin[j] = cn;
            ho[j] = ov * tanhf(cn);
        }
        cp[g4] = make_float4(cin[0], cin[1], cin[2], cin[3]);
        __nv_bfloat16 h0 = __float2bfloat16(ho[0]), h1 = __float2bfloat16(ho[1]);
        __nv_bfloat16 h2 = __float2bfloat16(ho[2]), h3 = __float2bfloat16(ho[3]);
        hwH[g4 * 2 + 0] = packbf(h0, h1);
        hwH[g4 * 2 + 1] = packbf(h2, h3);
        hwL[g4 * 2 + 0] = packbf(__float2bfloat16(ho[0] - __bfloat162float(h0)),
                                 __float2bfloat16(ho[1] - __bfloat162float(h1)));
        hwL[g4 * 2 + 1] = packbf(__float2bfloat16(ho[2] - __bfloat162float(h2)),
                                 __float2bfloat16(ho[3] - __bfloat162float(h3)));
        if (finalstep) *(float4*)(fp + g4 * 4) = make_float4(ho[0], ho[1], ho[2], ho[3]);
    }
    *(uint4*)hip       = make_uint4(hwH[0], hwH[1], hwH[2], hwH[3]);
    *(uint4*)(hip + 8) = make_uint4(hwH[4], hwH[5], hwH[6], hwH[7]);
    *(uint4*)lop       = make_uint4(hwL[0], hwL[1], hwL[2], hwL[3]);
    *(uint4*)(lop + 8) = make_uint4(hwL[4], hwL[5], hwL[6], hwL[7]);
}

// ---------------------------------------------------------------------------
// fc1 (fp32 SIMT): g_fc1 = leaky( leaky([hf|hb]) @ fc1_w.T + fc1_b )
// ---------------------------------------------------------------------------
__global__ void __launch_bounds__(256) fc1_gemm(const float* __restrict__ fc1_w,
                                                const float* __restrict__ fc1_b)
{
    __shared__ float As[16][64];
    __shared__ float Bs[16][64];
    const int tid = threadIdx.x;
    const int lr = tid >> 2;
    const int lc = (tid & 3) << 2;
    const int m0 = blockIdx.y * 64, n0 = blockIdx.x * 64;
    const int ty = tid >> 4, tx = tid & 15;
    float acc[4][4] = {};

    for (int k0 = 0; k0 < 2 * Hh; k0 += 16) {
        const int n = m0 + lr;
        const int kk = k0 + lc;
        const float* src = (kk < Hh) ? (g_hf + (size_t)n * Hh + kk)
                                     : (g_hb + (size_t)n * Hh + (kk - Hh));
        float4 a = *(const float4*)src;
        a.x = leakyf_(a.x); a.y = leakyf_(a.y); a.z = leakyf_(a.z); a.w = leakyf_(a.w);
        As[lc + 0][lr] = a.x; As[lc + 1][lr] = a.y; As[lc + 2][lr] = a.z; As[lc + 3][lr] = a.w;
        float4 b = *(const float4*)(fc1_w + (size_t)(n0 + lr) * (2 * Hh) + k0 + lc);
        Bs[lc + 0][lr] = b.x; Bs[lc + 1][lr] = b.y; Bs[lc + 2][lr] = b.z; Bs[lc + 3][lr] = b.w;
        __syncthreads();
#pragma unroll
        for (int kkk = 0; kkk < 16; kkk++) {
            float4 av = *(const float4*)&As[kkk][ty << 2];
            float4 bv = *(const float4*)&Bs[kkk][tx << 2];
            acc[0][0] += av.x * bv.x; acc[0][1] += av.x * bv.y; acc[0][2] += av.x * bv.z; acc[0][3] += av.x * bv.w;
            acc[1][0] += av.y * bv.x; acc[1][1] += av.y * bv.y; acc[1][2] += av.y * bv.z; acc[1][3] += av.y * bv.w;
            acc[2][0] += av.z * bv.x; acc[2][1] += av.z * bv.y; acc[2][2] += av.z * bv.z; acc[2][3] += av.z * bv.w;
            acc[3][0] += av.w * bv.x; acc[3][1] += av.w * bv.y; acc[3][2] += av.w * bv.z; acc[3][3] += av.w * bv.w;
        }
        __syncthreads();
    }

    const int cbase = n0 + (tx << 2);
    const float4 fb = *(const float4*)(fc1_b + cbase);
#pragma unroll
    for (int i = 0; i < 4; i++) {
        const int m = m0 + (ty << 2) + i;
        float4 v = make_float4(leakyf_(acc[i][0] + fb.x), leakyf_(acc[i][1] + fb.y),
                               leakyf_(acc[i][2] + fb.z), leakyf_(acc[i][3] + fb.w));
        *(float4*)(g_fc1 + (size_t)m * FHh + cbase) = v;
    }
}

__global__ void __launch_bounds__(128) fc2_kernel(const float* __restrict__ w,
                                                  const float* __restrict__ b,
                                                  float* __restrict__ out)
{
    const int n = blockIdx.x;
    const int t = threadIdx.x;
    const float* row = g_fc1 + (size_t)n * FHh;
    float s = 0.f;
#pragma unroll
    for (int j = t; j < FHh; j += 128) s += row[j] * w[j];
#pragma unroll
    for (int o = 16; o > 0; o >>= 1) s += __shfl_xor_sync(0xffffffffu, s, o);
    __shared__ float ws[4];
    if ((t & 31) == 0) ws[t >> 5] = s;
    __syncthreads();
    if (t == 0) {
        const float tot = ws[0] + ws[1] + ws[2] + ws[3];
        out[n] = 1.0f / (1.0f + expf(-(tot + b[0])));
    }
}

// ---------------------------------------------------------------------------
extern "C" void kernel_launch(void* const* d_in, const int* in_sizes, int n_in,
                              void* d_out, int out_size)
{
    const int*   x      = (const int*)  d_in[0];
    const float* embed  = (const float*)d_in[1];
    const float* Wih_f  = (const float*)d_in[2];
    const float* Whh_f  = (const float*)d_in[3];
    const float* bih_f  = (const float*)d_in[4];
    const float* bhh_f  = (const float*)d_in[5];
    const float* Wih_b  = (const float*)d_in[6];
    const float* Whh_b  = (const float*)d_in[7];
    const float* bih_b  = (const float*)d_in[8];
    const float* bhh_b  = (const float*)d_in[9];
    const float* fc1_w  = (const float*)d_in[10];
    const float* fc1_b  = (const float*)d_in[11];
    const float* fc2_w  = (const float*)d_in[12];
    const float* fc2_b  = (const float*)d_in[13];
    float* out = (float*)d_out;

    cudaFuncSetAttribute(gates_mma, cudaFuncAttributeMaxDynamicSharedMemorySize, GM_SMEM);

    prep_whh<<<256, 256>>>(Whh_f, Whh_b, bih_f, bhh_f, bih_b, bhh_b);
    pv_gemm<<<dim3(G4H / 64, Vv / 64), 256>>>(embed, Wih_f, 0);
    pv_gemm<<<dim3(G4H / 64, Vv / 64), 256>>>(embed, Wih_b, 1);
    zero_state<<<16384, 256>>>();

    for (int k = 0; k <= WSw; k++) {
        gates_mma<<<dim3(8, NTOK / 128, 2), 256, GM_SMEM>>>(x, k);
    }

    fc1_gemm<<<dim3(FHh / 64, NTOK / 64), 256>>>(fc1_w, fc1_b);
    fc2_kernel<<<NTOK, 128>>>(fc2_w, fc2_b, out);
}